// round 14
// baseline (speedup 1.0000x reference)
#include <cuda_runtime.h>
#include <cstdint>
#include <math.h>

#define NEG_INF_F __int_as_float(0xff800000)

#define NNODES 169343
#define HDIM   256
#define FIN    128
#define COUT   40
#define EPS    1e-5f
#define EMAX   2500000

// ---------------- scratch (no allocations allowed) ----------------
__device__ float g_h  [(size_t)NNODES * HDIM];   // GEMM out / gather src
__device__ float g_acc[(size_t)NNODES * HDIM];   // conv1 accumulator (raw, kept for residual)
__device__ float g_hin[(size_t)NNODES * HDIM];   // conv2 accumulator / final logits
__device__ float g_dinv[NNODES];
__device__ int   g_cnt [NNODES];
__device__ int   g_rowoff[NNODES + 1];
__device__ int   g_cursor[NNODES];
__device__ int   g_blocksum[512];
__device__ int   g_csr_src[EMAX];
__device__ float g_csr_w [EMAX];
__device__ float g_bnsum[HDIM];
__device__ float g_bnsq [HDIM];
__device__ float g_scale1[HDIM];
__device__ float g_shift1[HDIM];
__device__ float g_scale2[HDIM];
__device__ float g_shift2[HDIM];

// ---------------- degree / norm ----------------
__global__ void cnt_zero(int* cnt) {
    int i = blockIdx.x * blockDim.x + threadIdx.x;
    if (i < NNODES) cnt[i] = 0;
}
__global__ void deg_hist(const int* __restrict__ dst, int* __restrict__ cnt, int E) {
    int e = blockIdx.x * blockDim.x + threadIdx.x;
    if (e < E) atomicAdd(&cnt[dst[e]], 1);
}
__global__ void dinv_k(const int* __restrict__ cnt, float* __restrict__ dinv) {
    int i = blockIdx.x * blockDim.x + threadIdx.x;
    if (i < NNODES) dinv[i] = rsqrtf((float)(cnt[i] + 1));
}

// ---------------- exclusive scan ----------------
__global__ void scan_block(const int* __restrict__ in, int* __restrict__ out,
                           int* __restrict__ bsum, int n)
{
    __shared__ int wsum[8];
    __shared__ int woff[8];
    int t = threadIdx.x;
    int base = blockIdx.x * 1024 + t * 4;
    int val[4], inc[4];
    int s = 0;
    #pragma unroll
    for (int k = 0; k < 4; k++) {
        val[k] = (base + k < n) ? in[base + k] : 0;
        s += val[k];
        inc[k] = s;
    }
    int lane = t & 31, wid = t >> 5;
    int x = s;
    #pragma unroll
    for (int o = 1; o < 32; o <<= 1) {
        int y = __shfl_up_sync(0xffffffffu, x, o);
        if (lane >= o) x += y;
    }
    if (lane == 31) wsum[wid] = x;
    __syncthreads();
    if (t == 0) {
        int a = 0;
        #pragma unroll
        for (int w = 0; w < 8; w++) { woff[w] = a; a += wsum[w]; }
        bsum[blockIdx.x] = a;
    }
    __syncthreads();
    int tb = woff[wid] + x - s;
    #pragma unroll
    for (int k = 0; k < 4; k++)
        if (base + k < n) out[base + k] = tb + inc[k] - val[k];
}
__global__ void scan_sums(int* __restrict__ bsum, int nb) {
    __shared__ int wsum[8];
    __shared__ int woff[8];
    int t = threadIdx.x;
    int v = (t < nb) ? bsum[t] : 0;
    int lane = t & 31, wid = t >> 5;
    int x = v;
    #pragma unroll
    for (int o = 1; o < 32; o <<= 1) {
        int y = __shfl_up_sync(0xffffffffu, x, o);
        if (lane >= o) x += y;
    }
    if (lane == 31) wsum[wid] = x;
    __syncthreads();
    if (t == 0) {
        int a = 0;
        #pragma unroll
        for (int w = 0; w < 8; w++) { woff[w] = a; a += wsum[w]; }
    }
    __syncthreads();
    if (t < nb) bsum[t] = woff[wid] + x - v;
}
__global__ void scan_add(int* __restrict__ out, const int* __restrict__ bsum, int n, int E) {
    int i = blockIdx.x * blockDim.x + threadIdx.x;
    if (i < n) out[i] += bsum[i >> 10];
    if (i == 0) out[n] = E;
}
__global__ void cursor_copy(const int* __restrict__ rowoff, int* __restrict__ cur) {
    int i = blockIdx.x * blockDim.x + threadIdx.x;
    if (i < NNODES) cur[i] = rowoff[i];
}
__global__ void csr_place(const int* __restrict__ src, const int* __restrict__ dst,
                          const float* __restrict__ dinv, int* __restrict__ cur,
                          int* __restrict__ csrc, float* __restrict__ cw, int E)
{
    int e = blockIdx.x * blockDim.x + threadIdx.x;
    if (e >= E) return;
    int s = src[e], d = dst[e];
    int pos = atomicAdd(&cur[d], 1);
    csrc[pos] = s;
    cw[pos] = dinv[s] * dinv[d];
}

// ---------------- tf32 split helpers ----------------
__device__ __forceinline__ void tf32split(float x, uint32_t& hi, uint32_t& lo) {
    uint32_t xb = __float_as_uint(x);
    uint32_t h = xb & 0xFFFFE000u;
    float l = x - __uint_as_float(h);
    uint32_t lb;
    asm("cvt.rna.tf32.f32 %0, %1;" : "=r"(lb) : "f"(l));
    hi = h; lo = lb;
}
__device__ __forceinline__ void mma_tf32(float* c, uint32_t a0, uint32_t a1,
                                         uint32_t a2, uint32_t a3,
                                         uint32_t b0, uint32_t b1) {
    asm volatile(
        "mma.sync.aligned.m16n8k8.row.col.f32.tf32.tf32.f32 "
        "{%0,%1,%2,%3}, {%4,%5,%6,%7}, {%8,%9}, {%0,%1,%2,%3};"
        : "+f"(c[0]), "+f"(c[1]), "+f"(c[2]), "+f"(c[3])
        : "r"(a0), "r"(a1), "r"(a2), "r"(a3), "r"(b0), "r"(b1));
}
__device__ __forceinline__ uint32_t smem_u32(const void* p) {
    return (uint32_t)__cvta_generic_to_shared(p);
}
__device__ __forceinline__ void cp_async16(uint32_t dst, const void* src, int sz) {
    asm volatile("cp.async.cg.shared.global [%0], [%1], 16, %2;"
                 :: "r"(dst), "l"(src), "r"(sz));
}
__device__ __forceinline__ float4 bnrelu4(float4 v, float4 s, float4 sh) {
    float4 r;
    r.x = fmaxf(fmaf(v.x, s.x, sh.x), 0.f);
    r.y = fmaxf(fmaf(v.y, s.y, sh.y), 0.f);
    r.z = fmaxf(fmaf(v.z, s.z, sh.z), 0.f);
    r.w = fmaxf(fmaf(v.w, s.w, sh.w), 0.f);
    return r;
}

// ---------------- tensor-core GEMM: 128x128x32, 3xTF32, cp.async pipeline, 2 CTA/SM ----------------
// A split to smem hi/lo; B split in registers from padded raw tile.
#define GBM 128
#define GBN 128
#define GBK 32
#define SST 136
#define RAW_A_F (GBM * GBK)      // 4096 floats, layout [m][k]
#define RAW_B_F (GBK * SST)      // 4352 floats, layout [k][n] padded
#define HL_F (GBK * SST)         // 4352 floats, layout [k][m] padded
#define GEMM_SMEM_BYTES ((2 * RAW_A_F + 2 * RAW_B_F + 2 * HL_F) * 4)

__global__ void __launch_bounds__(256, 2) gemm_tf32(
    const float* __restrict__ A, const float* __restrict__ B, float* __restrict__ C,
    int M, int K, int Nc,
    const float* __restrict__ Asc, const float* __restrict__ Ash)
{
    extern __shared__ float smem[];
    float* rawA = smem;                       // [2][GBM][GBK]
    float* rawB = rawA + 2 * RAW_A_F;         // [2][GBK][SST]
    float* Ahi = rawB + 2 * RAW_B_F;          // [GBK][SST]
    float* Alo = Ahi + HL_F;
#define AHI(k, m) Ahi[(k) * SST + (m)]
#define ALO(k, m) Alo[(k) * SST + (m)]

    int tid = threadIdx.x;
    int warp = tid >> 5, lane = tid & 31;
    int m0 = blockIdx.y * GBM, n0 = blockIdx.x * GBN;
    int wm = (warp >> 2) * 64;
    int wn = (warp & 3) * 32;
    int grp = lane >> 2, tig = lane & 3;

    float c[4][4][4];
    #pragma unroll
    for (int i = 0; i < 4; i++)
        #pragma unroll
        for (int j = 0; j < 4; j++)
            #pragma unroll
            for (int r = 0; r < 4; r++) c[i][j][r] = 0.f;

    // per-thread copy slots: 4 float4 of A + 4 float4 of B per tile
    int am[4], ak[4], brr[4], bcc[4];
    #pragma unroll
    for (int j = 0; j < 4; j++) {
        int ia = tid + 256 * j;
        am[j] = ia >> 3;  ak[j] = (ia & 7) << 2;
        brr[j] = ia >> 5; bcc[j] = (ia & 31) << 2;
    }
    int nk = K / GBK;

    // prologue: tile 0
    #pragma unroll
    for (int j = 0; j < 4; j++) {
        cp_async16(smem_u32(rawA + am[j] * GBK + ak[j]),
                   A + (size_t)(m0 + am[j]) * K + ak[j], (m0 + am[j] < M) ? 16 : 0);
        cp_async16(smem_u32(rawB + brr[j] * SST + bcc[j]),
                   B + (size_t)brr[j] * Nc + n0 + bcc[j], 16);
    }
    asm volatile("cp.async.commit_group;");

    for (int t = 0; t < nk; t++) {
        int buf = t & 1;
        bool more = (t + 1 < nk);
        if (more) {
            int k0 = (t + 1) * GBK;
            int nb = buf ^ 1;
            #pragma unroll
            for (int j = 0; j < 4; j++) {
                cp_async16(smem_u32(rawA + nb * RAW_A_F + am[j] * GBK + ak[j]),
                           A + (size_t)(m0 + am[j]) * K + k0 + ak[j], (m0 + am[j] < M) ? 16 : 0);
                cp_async16(smem_u32(rawB + nb * RAW_B_F + brr[j] * SST + bcc[j]),
                           B + (size_t)(k0 + brr[j]) * Nc + n0 + bcc[j], 16);
            }
            asm volatile("cp.async.commit_group;");
            asm volatile("cp.async.wait_group 1;");
        } else {
            asm volatile("cp.async.wait_group 0;");
        }
        __syncthreads();   // raw[buf] visible; previous compute done

        // split A raw -> hi/lo (optionally fused BN+ReLU)
        {
            const float* ra = rawA + buf * RAW_A_F;
            #pragma unroll
            for (int j = 0; j < 4; j++) {
                float4 a = *(const float4*)(ra + am[j] * GBK + ak[j]);
                if (Asc) {
                    int cb = t * GBK + ak[j];
                    a = bnrelu4(a, *(const float4*)(Asc + cb), *(const float4*)(Ash + cb));
                }
                uint32_t h, l;
                tf32split(a.x, h, l); AHI(ak[j] + 0, am[j]) = __uint_as_float(h); ALO(ak[j] + 0, am[j]) = __uint_as_float(l);
                tf32split(a.y, h, l); AHI(ak[j] + 1, am[j]) = __uint_as_float(h); ALO(ak[j] + 1, am[j]) = __uint_as_float(l);
                tf32split(a.z, h, l); AHI(ak[j] + 2, am[j]) = __uint_as_float(h); ALO(ak[j] + 2, am[j]) = __uint_as_float(l);
                tf32split(a.w, h, l); AHI(ak[j] + 3, am[j]) = __uint_as_float(h); ALO(ak[j] + 3, am[j]) = __uint_as_float(l);
            }
        }
        __syncthreads();

        // compute 4 x k8; B read raw + register split
        const float* rb = rawB + buf * RAW_B_F;
        #pragma unroll
        for (int h8 = 0; h8 < 4; h8++) {
            int k8 = h8 * 8;
            uint32_t bh[4][2], bl[4][2];
            #pragma unroll
            for (int ni = 0; ni < 4; ni++) {
                int n = wn + 8 * ni + grp;
                float r0 = rb[(k8 + tig) * SST + n];
                float r1 = rb[(k8 + tig + 4) * SST + n];
                tf32split(r0, bh[ni][0], bl[ni][0]);
                tf32split(r1, bh[ni][1], bl[ni][1]);
            }
            #pragma unroll
            for (int mi = 0; mi < 4; mi++) {
                int m = wm + 16 * mi + grp;
                uint32_t ah0 = __float_as_uint(AHI(k8 + tig, m));
                uint32_t ah1 = __float_as_uint(AHI(k8 + tig, m + 8));
                uint32_t ah2 = __float_as_uint(AHI(k8 + tig + 4, m));
                uint32_t ah3 = __float_as_uint(AHI(k8 + tig + 4, m + 8));
                uint32_t al0 = __float_as_uint(ALO(k8 + tig, m));
                uint32_t al1 = __float_as_uint(ALO(k8 + tig, m + 8));
                uint32_t al2 = __float_as_uint(ALO(k8 + tig + 4, m));
                uint32_t al3 = __float_as_uint(ALO(k8 + tig + 4, m + 8));
                #pragma unroll
                for (int ni = 0; ni < 4; ni++) {
                    mma_tf32(c[mi][ni], ah0, ah1, ah2, ah3, bh[ni][0], bh[ni][1]);
                    mma_tf32(c[mi][ni], ah0, ah1, ah2, ah3, bl[ni][0], bl[ni][1]);
                    mma_tf32(c[mi][ni], al0, al1, al2, al3, bh[ni][0], bh[ni][1]);
                }
            }
        }
    }

    #pragma unroll
    for (int mi = 0; mi < 4; mi++) {
        int r0 = m0 + wm + 16 * mi + grp;
        int r1 = r0 + 8;
        #pragma unroll
        for (int ni = 0; ni < 4; ni++) {
            int cc = n0 + wn + 8 * ni + 2 * tig;
            if (r0 < M) *(float2*)(C + (size_t)r0 * Nc + cc) = make_float2(c[mi][ni][0], c[mi][ni][1]);
            if (r1 < M) *(float2*)(C + (size_t)r1 * Nc + cc) = make_float2(c[mi][ni][2], c[mi][ni][3]);
        }
    }
#undef AHI
#undef ALO
}

// ---------------- small SGEMM for layer 3 (N=40), fused A = relu(bn2(A)) + relu(bn1(R)) ----------------
#define BM 64
#define BN 64
#define BKK 16
__global__ void __launch_bounds__(256) sgemm64(
    const float* __restrict__ A, const float* __restrict__ B, float* __restrict__ C,
    int M, int K, int Nc,
    const float* __restrict__ Asc, const float* __restrict__ Ash,
    const float* __restrict__ R, const float* __restrict__ Rsc, const float* __restrict__ Rsh)
{
    __shared__ float As[BKK][BM];
    __shared__ float Bs[BKK][BN];
    int tid = threadIdx.x;
    int tx = tid & 15, ty = tid >> 4;
    int m0 = blockIdx.y * BM;
    int n0 = blockIdx.x * BN;
    float acc[4][4] = {};

    int ar = tid >> 2;
    int ak = (tid & 3) * 4;
    int br = tid >> 4;
    int bc = (tid & 15) * 4;

    for (int k0 = 0; k0 < K; k0 += BKK) {
        float4 av = make_float4(0.f, 0.f, 0.f, 0.f);
        int am = m0 + ar;
        if (am < M) {
            av = *(const float4*)(A + (size_t)am * K + k0 + ak);
            int cb = k0 + ak;
            av = bnrelu4(av, *(const float4*)(Asc + cb), *(const float4*)(Ash + cb));
            float4 rv = *(const float4*)(R + (size_t)am * K + cb);
            float4 rr = bnrelu4(rv, *(const float4*)(Rsc + cb), *(const float4*)(Rsh + cb));
            av.x += rr.x; av.y += rr.y; av.z += rr.z; av.w += rr.w;
        }
        As[ak + 0][ar] = av.x; As[ak + 1][ar] = av.y;
        As[ak + 2][ar] = av.z; As[ak + 3][ar] = av.w;

        float4 bv = make_float4(0.f, 0.f, 0.f, 0.f);
        if (n0 + bc < Nc) bv = *(const float4*)(B + (size_t)(k0 + br) * Nc + n0 + bc);
        *(float4*)&Bs[br][bc] = bv;
        __syncthreads();

        #pragma unroll
        for (int kk = 0; kk < BKK; kk++) {
            float a[4], b[4];
            *(float4*)a = *(const float4*)&As[kk][ty * 4];
            *(float4*)b = *(const float4*)&Bs[kk][tx * 4];
            #pragma unroll
            for (int i = 0; i < 4; i++)
                #pragma unroll
                for (int j = 0; j < 4; j++)
                    acc[i][j] += a[i] * b[j];
        }
        __syncthreads();
    }
    #pragma unroll
    for (int i = 0; i < 4; i++) {
        int m = m0 + ty * 4 + i;
        if (m >= M) continue;
        #pragma unroll
        for (int j = 0; j < 4; j++) {
            int n = n0 + tx * 4 + j;
            if (n < Nc) C[(size_t)m * Nc + n] = acc[i][j];
        }
    }
}

// ---------------- CSR gather (float4 / 64 threads per node) + fused BN stats ----------------
__global__ void __launch_bounds__(64) gather256_bn(
    const float* __restrict__ h, const float* __restrict__ dinv,
    const float* __restrict__ bias, const int* __restrict__ rowoff,
    const int* __restrict__ csrc, const float* __restrict__ cw,
    float* __restrict__ out)
{
    __shared__ int   ss[64];
    __shared__ float sw[64];
    int t = threadIdx.x;
    int c4 = t * 4;
    float4 bsc = *(const float4*)(bias + c4);
    float4 ssum = make_float4(0.f, 0.f, 0.f, 0.f);
    float4 ssq  = make_float4(0.f, 0.f, 0.f, 0.f);
    for (int i = blockIdx.x; i < NNODES; i += gridDim.x) {
        int beg = rowoff[i], end = rowoff[i + 1];
        float di = dinv[i];
        float w0 = di * di;
        float4 hv = *(const float4*)(h + (size_t)i * HDIM + c4);
        float4 acc;
        acc.x = fmaf(w0, hv.x, bsc.x);
        acc.y = fmaf(w0, hv.y, bsc.y);
        acc.z = fmaf(w0, hv.z, bsc.z);
        acc.w = fmaf(w0, hv.w, bsc.w);
        for (int off = beg; off < end; off += 64) {
            int m = min(64, end - off);
            if (t < m) { ss[t] = csrc[off + t]; sw[t] = cw[off + t]; }
            __syncthreads();
            int j = 0;
            for (; j + 4 <= m; j += 4) {
                float4 a0 = *(const float4*)(h + (size_t)ss[j + 0] * HDIM + c4);
                float4 a1 = *(const float4*)(h + (size_t)ss[j + 1] * HDIM + c4);
                float4 a2 = *(const float4*)(h + (size_t)ss[j + 2] * HDIM + c4);
                float4 a3 = *(const float4*)(h + (size_t)ss[j + 3] * HDIM + c4);
                float w1 = sw[j + 0], w2 = sw[j + 1], w3 = sw[j + 2], w4 = sw[j + 3];
                acc.x = fmaf(w1, a0.x, acc.x); acc.y = fmaf(w1, a0.y, acc.y);
                acc.z = fmaf(w1, a0.z, acc.z); acc.w = fmaf(w1, a0.w, acc.w);
                acc.x = fmaf(w2, a1.x, acc.x); acc.y = fmaf(w2, a1.y, acc.y);
                acc.z = fmaf(w2, a1.z, acc.z); acc.w = fmaf(w2, a1.w, acc.w);
                acc.x = fmaf(w3, a2.x, acc.x); acc.y = fmaf(w3, a2.y, acc.y);
                acc.z = fmaf(w3, a2.z, acc.z); acc.w = fmaf(w3, a2.w, acc.w);
                acc.x = fmaf(w4, a3.x, acc.x); acc.y = fmaf(w4, a3.y, acc.y);
                acc.z = fmaf(w4, a3.z, acc.z); acc.w = fmaf(w4, a3.w, acc.w);
            }
            for (; j < m; j++) {
                float4 a0 = *(const float4*)(h + (size_t)ss[j] * HDIM + c4);
                float w1 = sw[j];
                acc.x = fmaf(w1, a0.x, acc.x); acc.y = fmaf(w1, a0.y, acc.y);
                acc.z = fmaf(w1, a0.z, acc.z); acc.w = fmaf(w1, a0.w, acc.w);
            }
            __syncthreads();
        }
        *(float4*)(out + (size_t)i * HDIM + c4) = acc;
        ssum.x += acc.x; ssum.y += acc.y; ssum.z += acc.z; ssum.w += acc.w;
        ssq.x = fmaf(acc.x, acc.x, ssq.x); ssq.y = fmaf(acc.y, acc.y, ssq.y);
        ssq.z = fmaf(acc.z, acc.z, ssq.z); ssq.w = fmaf(acc.w, acc.w, ssq.w);
    }
    atomicAdd(&g_bnsum[c4 + 0], ssum.x); atomicAdd(&g_bnsum[c4 + 1], ssum.y);
    atomicAdd(&g_bnsum[c4 + 2], ssum.z); atomicAdd(&g_bnsum[c4 + 3], ssum.w);
    atomicAdd(&g_bnsq[c4 + 0], ssq.x);  atomicAdd(&g_bnsq[c4 + 1], ssq.y);
    atomicAdd(&g_bnsq[c4 + 2], ssq.z);  atomicAdd(&g_bnsq[c4 + 3], ssq.w);
}

__global__ void __launch_bounds__(64) gather40(
    const float* __restrict__ h, const float* __restrict__ dinv,
    const float* __restrict__ bias, const int* __restrict__ rowoff,
    const int* __restrict__ csrc, const float* __restrict__ cw,
    float* __restrict__ out)
{
    __shared__ int   ss[64];
    __shared__ float sw[64];
    int i = blockIdx.x;
    int c = threadIdx.x;
    int beg = rowoff[i], end = rowoff[i + 1];
    float di = dinv[i];
    float acc = 0.f;
    if (c < COUT) acc = fmaf(di * di, h[(size_t)i * COUT + c], bias[c]);
    for (int off = beg; off < end; off += 64) {
        int m = min(64, end - off);
        if (c < m) { ss[c] = csrc[off + c]; sw[c] = cw[off + c]; }
        __syncthreads();
        if (c < COUT) {
            int j = 0;
            for (; j + 4 <= m; j += 4) {
                float a0 = h[(size_t)ss[j + 0] * COUT + c];
                float a1 = h[(size_t)ss[j + 1] * COUT + c];
                float a2 = h[(size_t)ss[j + 2] * COUT + c];
                float a3 = h[(size_t)ss[j + 3] * COUT + c];
                acc = fmaf(sw[j + 0], a0, acc);
                acc = fmaf(sw[j + 1], a1, acc);
                acc = fmaf(sw[j + 2], a2, acc);
                acc = fmaf(sw[j + 3], a3, acc);
            }
            for (; j < m; j++)
                acc = fmaf(sw[j], h[(size_t)ss[j] * COUT + c], acc);
        }
        __syncthreads();
    }
    if (c < COUT) out[(size_t)i * COUT + c] = acc;
}

// ---------------- batchnorm ----------------
__global__ void bn_zero() {
    int c = threadIdx.x;
    g_bnsum[c] = 0.f;
    g_bnsq[c]  = 0.f;
}
__global__ void bn_final(const float* __restrict__ gamma, const float* __restrict__ beta,
                         float* __restrict__ outScale, float* __restrict__ outShift) {
    int c = threadIdx.x;
    float invn = 1.f / (float)NNODES;
    float mean = g_bnsum[c] * invn;
    float var  = g_bnsq[c] * invn - mean * mean;
    float sc = gamma[c] * rsqrtf(var + EPS);
    outScale[c] = sc;
    outShift[c] = beta[c] - mean * sc;
}

// ---------------- log_softmax over 40 classes ----------------
__global__ void logsoftmax40(const float* __restrict__ x, float* __restrict__ out) {
    int g = blockIdx.x * blockDim.x + threadIdx.x;
    int row = g >> 5, lane = g & 31;
    if (row >= NNODES) return;
    const float* xr = x + (size_t)row * COUT;
    float v0 = xr[lane];
    float v1 = (lane + 32 < COUT) ? xr[lane + 32] : NEG_INF_F;
    float m = fmaxf(v0, v1);
    #pragma unroll
    for (int o = 16; o; o >>= 1) m = fmaxf(m, __shfl_xor_sync(0xffffffffu, m, o));
    float e0 = __expf(v0 - m);
    float e1 = (lane + 32 < COUT) ? __expf(v1 - m) : 0.f;
    float s = e0 + e1;
    #pragma unroll
    for (int o = 16; o; o >>= 1) s += __shfl_xor_sync(0xffffffffu, s, o);
    float ls = logf(s);
    out[(size_t)row * COUT + lane] = v0 - m - ls;
    if (lane + 32 < COUT) out[(size_t)row * COUT + lane + 32] = v1 - m - ls;
}

// ---------------- driver ----------------
extern "C" void kernel_launch(void* const* d_in, const int* in_sizes, int n_in,
                              void* d_out, int out_size)
{
    const float* x   = (const float*)d_in[0];
    const int*   ei  = (const int*)  d_in[1];
    const float* W1  = (const float*)d_in[2];
    const float* b1  = (const float*)d_in[3];
    const float* g1  = (const float*)d_in[4];
    const float* be1 = (const float*)d_in[5];
    const float* W2  = (const float*)d_in[6];
    const float* b2  = (const float*)d_in[7];
    const float* g2  = (const float*)d_in[8];
    const float* be2 = (const float*)d_in[9];
    const float* W3  = (const float*)d_in[10];
    const float* b3  = (const float*)d_in[11];
    float* out = (float*)d_out;

    int E = in_sizes[1] / 2;
    const int* src = ei;
    const int* dst = ei + E;

    float *h, *acc, *hin, *dinv, *cw, *sc1, *sh1, *sc2, *sh2;
    int *cnt, *rowoff, *cursor, *bsum, *csrc;
    cudaGetSymbolAddress((void**)&h,      g_h);
    cudaGetSymbolAddress((void**)&acc,    g_acc);
    cudaGetSymbolAddress((void**)&hin,    g_hin);
    cudaGetSymbolAddress((void**)&dinv,   g_dinv);
    cudaGetSymbolAddress((void**)&cnt,    g_cnt);
    cudaGetSymbolAddress((void**)&rowoff, g_rowoff);
    cudaGetSymbolAddress((void**)&cursor, g_cursor);
    cudaGetSymbolAddress((void**)&bsum,   g_blocksum);
    cudaGetSymbolAddress((void**)&csrc,   g_csr_src);
    cudaGetSymbolAddress((void**)&cw,     g_csr_w);
    cudaGetSymbolAddress((void**)&sc1,    g_scale1);
    cudaGetSymbolAddress((void**)&sh1,    g_shift1);
    cudaGetSymbolAddress((void**)&sc2,    g_scale2);
    cudaGetSymbolAddress((void**)&sh2,    g_shift2);

    cudaFuncSetAttribute(gemm_tf32, cudaFuncAttributeMaxDynamicSharedMemorySize, GEMM_SMEM_BYTES);

    const int T = 256;
    int nbN  = (NNODES + T - 1) / T;
    int nbE  = (E + T - 1) / T;
    int nbRow = (int)(((long long)NNODES * 32 + T - 1) / T);
    int nbScan = (NNODES + 1023) / 1024;
    dim3 gemmGrid(HDIM / GBN, (NNODES + GBM - 1) / GBM);
    dim3 gemmGrid40(1, (NNODES + 63) / 64);
    const int GB = 4096;

    // ---- degree/norm, then L1 GEMM early (profiled slot), then CSR ----
    cnt_zero<<<nbN, T>>>(cnt);
    deg_hist<<<nbE, T>>>(dst, cnt, E);
    dinv_k<<<nbN, T>>>(cnt, dinv);

    gemm_tf32<<<gemmGrid, T, GEMM_SMEM_BYTES>>>(x, W1, h, NNODES, FIN, HDIM, nullptr, nullptr);

    scan_block<<<nbScan, 256>>>(cnt, rowoff, bsum, NNODES);
    scan_sums<<<1, 256>>>(bsum, nbScan);
    scan_add<<<nbN, T>>>(rowoff, bsum, NNODES, E);
    cursor_copy<<<nbN, T>>>(rowoff, cursor);
    csr_place<<<nbE, T>>>(src, dst, dinv, cursor, csrc, cw, E);

    // ---- layer 1: gather -> acc (raw conv1 out, kept for residual) ----
    bn_zero<<<1, HDIM>>>();
    gather256_bn<<<GB, 64>>>(h, dinv, b1, rowoff, csrc, cw, acc);
    bn_final<<<1, HDIM>>>(g1, be1, sc1, sh1);

    // ---- layer 2: GEMM reads acc with fused bn1+relu; gather -> hin (raw conv2 out) ----
    gemm_tf32<<<gemmGrid, T, GEMM_SMEM_BYTES>>>(acc, W2, h, NNODES, HDIM, HDIM, sc1, sh1);
    bn_zero<<<1, HDIM>>>();
    gather256_bn<<<GB, 64>>>(h, dinv, b2, rowoff, csrc, cw, hin);
    bn_final<<<1, HDIM>>>(g2, be2, sc2, sh2);

    // ---- layer 3: A = relu(bn2(hin)) + relu(bn1(acc)) fused in sgemm64; C -> h (N x 40) ----
    sgemm64<<<gemmGrid40, T>>>(hin, W3, h, NNODES, HDIM, COUT, sc2, sh2, acc, sc1, sh1);
    gather40<<<NNODES, 64>>>(h, dinv, b3, rowoff, csrc, cw, hin);   // hin reused as N x 40
    logsoftmax40<<<nbRow, T>>>(hin, out);
}

// round 15
// speedup vs baseline: 1.0098x; 1.0098x over previous
#include <cuda_runtime.h>
#include <cstdint>
#include <math.h>

#define NEG_INF_F __int_as_float(0xff800000)

#define NNODES 169343
#define HDIM   256
#define FIN    128
#define COUT   40
#define EPS    1e-5f
#define EMAX   2500000

// ---------------- scratch (no allocations allowed) ----------------
__device__ float g_h  [(size_t)NNODES * HDIM];
__device__ float g_acc[(size_t)NNODES * HDIM];
__device__ float g_hin[(size_t)NNODES * HDIM];
__device__ float g_dinv[NNODES];
__device__ int   g_cnt [NNODES];
__device__ int   g_rowoff[NNODES + 1];
__device__ int   g_cursor[NNODES];
__device__ int   g_blocksum[512];
__device__ int   g_csr_src[EMAX];
__device__ float g_csr_w [EMAX];
__device__ float g_bnsum[HDIM];
__device__ float g_bnsq [HDIM];
__device__ float g_scale1[HDIM];
__device__ float g_shift1[HDIM];
__device__ float g_scale2[HDIM];
__device__ float g_shift2[HDIM];

// ---------------- degree / norm ----------------
__global__ void cnt_zero(int* cnt) {
    int i = blockIdx.x * blockDim.x + threadIdx.x;
    if (i < NNODES) cnt[i] = 0;
}
__global__ void deg_hist(const int* __restrict__ dst, int* __restrict__ cnt, int E) {
    int e = blockIdx.x * blockDim.x + threadIdx.x;
    if (e < E) atomicAdd(&cnt[dst[e]], 1);
}
__global__ void dinv_k(const int* __restrict__ cnt, float* __restrict__ dinv) {
    int i = blockIdx.x * blockDim.x + threadIdx.x;
    if (i < NNODES) dinv[i] = rsqrtf((float)(cnt[i] + 1));
}

// ---------------- exclusive scan ----------------
__global__ void scan_block(const int* __restrict__ in, int* __restrict__ out,
                           int* __restrict__ bsum, int n)
{
    __shared__ int wsum[8];
    __shared__ int woff[8];
    int t = threadIdx.x;
    int base = blockIdx.x * 1024 + t * 4;
    int val[4], inc[4];
    int s = 0;
    #pragma unroll
    for (int k = 0; k < 4; k++) {
        val[k] = (base + k < n) ? in[base + k] : 0;
        s += val[k];
        inc[k] = s;
    }
    int lane = t & 31, wid = t >> 5;
    int x = s;
    #pragma unroll
    for (int o = 1; o < 32; o <<= 1) {
        int y = __shfl_up_sync(0xffffffffu, x, o);
        if (lane >= o) x += y;
    }
    if (lane == 31) wsum[wid] = x;
    __syncthreads();
    if (t == 0) {
        int a = 0;
        #pragma unroll
        for (int w = 0; w < 8; w++) { woff[w] = a; a += wsum[w]; }
        bsum[blockIdx.x] = a;
    }
    __syncthreads();
    int tb = woff[wid] + x - s;
    #pragma unroll
    for (int k = 0; k < 4; k++)
        if (base + k < n) out[base + k] = tb + inc[k] - val[k];
}
__global__ void scan_sums(int* __restrict__ bsum, int nb) {
    __shared__ int wsum[8];
    __shared__ int woff[8];
    int t = threadIdx.x;
    int v = (t < nb) ? bsum[t] : 0;
    int lane = t & 31, wid = t >> 5;
    int x = v;
    #pragma unroll
    for (int o = 1; o < 32; o <<= 1) {
        int y = __shfl_up_sync(0xffffffffu, x, o);
        if (lane >= o) x += y;
    }
    if (lane == 31) wsum[wid] = x;
    __syncthreads();
    if (t == 0) {
        int a = 0;
        #pragma unroll
        for (int w = 0; w < 8; w++) { woff[w] = a; a += wsum[w]; }
    }
    __syncthreads();
    if (t < nb) bsum[t] = woff[wid] + x - v;
}
__global__ void scan_add(int* __restrict__ out, const int* __restrict__ bsum, int n, int E) {
    int i = blockIdx.x * blockDim.x + threadIdx.x;
    if (i < n) out[i] += bsum[i >> 10];
    if (i == 0) out[n] = E;
}
__global__ void cursor_copy(const int* __restrict__ rowoff, int* __restrict__ cur) {
    int i = blockIdx.x * blockDim.x + threadIdx.x;
    if (i < NNODES) cur[i] = rowoff[i];
}
__global__ void csr_place(const int* __restrict__ src, const int* __restrict__ dst,
                          const float* __restrict__ dinv, int* __restrict__ cur,
                          int* __restrict__ csrc, float* __restrict__ cw, int E)
{
    int e = blockIdx.x * blockDim.x + threadIdx.x;
    if (e >= E) return;
    int s = src[e], d = dst[e];
    int pos = atomicAdd(&cur[d], 1);
    csrc[pos] = s;
    cw[pos] = dinv[s] * dinv[d];
}

// ---------------- tf32 split helpers ----------------
__device__ __forceinline__ void tf32split(float x, uint32_t& hi, uint32_t& lo) {
    uint32_t xb = __float_as_uint(x);
    uint32_t h = xb & 0xFFFFE000u;
    float l = x - __uint_as_float(h);
    uint32_t lb;
    asm("cvt.rna.tf32.f32 %0, %1;" : "=r"(lb) : "f"(l));
    hi = h; lo = lb;
}
__device__ __forceinline__ void mma_tf32(float* c, uint32_t a0, uint32_t a1,
                                         uint32_t a2, uint32_t a3,
                                         uint32_t b0, uint32_t b1) {
    asm volatile(
        "mma.sync.aligned.m16n8k8.row.col.f32.tf32.tf32.f32 "
        "{%0,%1,%2,%3}, {%4,%5,%6,%7}, {%8,%9}, {%0,%1,%2,%3};"
        : "+f"(c[0]), "+f"(c[1]), "+f"(c[2]), "+f"(c[3])
        : "r"(a0), "r"(a1), "r"(a2), "r"(a3), "r"(b0), "r"(b1));
}
__device__ __forceinline__ uint32_t smem_u32(const void* p) {
    return (uint32_t)__cvta_generic_to_shared(p);
}
__device__ __forceinline__ void cp_async16(uint32_t dst, const void* src, int sz) {
    asm volatile("cp.async.cg.shared.global [%0], [%1], 16, %2;"
                 :: "r"(dst), "l"(src), "r"(sz));
}
__device__ __forceinline__ float4 bnrelu4(float4 v, float4 s, float4 sh) {
    float4 r;
    r.x = fmaxf(fmaf(v.x, s.x, sh.x), 0.f);
    r.y = fmaxf(fmaf(v.y, s.y, sh.y), 0.f);
    r.z = fmaxf(fmaf(v.z, s.z, sh.z), 0.f);
    r.w = fmaxf(fmaf(v.w, s.w, sh.w), 0.f);
    return r;
}

// ---------------- tensor-core GEMM: 128x128x16, 3xTF32, cp.async pipeline, 2 CTA/SM ----------------
// (R13 version — smem hi/lo for both A and B; race-free double buffering)
#define GBM 128
#define GBN 128
#define GBK 16
#define SST 136
#define RAW_A_F (GBM * GBK)
#define RAW_B_F (GBK * GBN)
#define HL_F (GBK * SST)
#define GEMM_SMEM_BYTES ((2 * RAW_A_F + 2 * RAW_B_F + 4 * HL_F) * 4)

__global__ void __launch_bounds__(256, 2) gemm_tf32(
    const float* __restrict__ A, const float* __restrict__ B, float* __restrict__ C,
    int M, int K, int Nc,
    const float* __restrict__ Asc, const float* __restrict__ Ash)
{
    extern __shared__ float smem[];
    float* rawA = smem;
    float* rawB = rawA + 2 * RAW_A_F;
    float* Ahi = rawB + 2 * RAW_B_F;
    float* Alo = Ahi + HL_F;
    float* Bhi = Alo + HL_F;
    float* Blo = Bhi + HL_F;
#define AHI(k, m) Ahi[(k) * SST + (m)]
#define ALO(k, m) Alo[(k) * SST + (m)]
#define BHI(k, n) Bhi[(k) * SST + (n)]
#define BLO(k, n) Blo[(k) * SST + (n)]

    int tid = threadIdx.x;
    int warp = tid >> 5, lane = tid & 31;
    int m0 = blockIdx.y * GBM, n0 = blockIdx.x * GBN;
    int wm = (warp >> 2) * 64;
    int wn = (warp & 3) * 32;
    int grp = lane >> 2, tig = lane & 3;

    float c[4][4][4];
    #pragma unroll
    for (int i = 0; i < 4; i++)
        #pragma unroll
        for (int j = 0; j < 4; j++)
            #pragma unroll
            for (int r = 0; r < 4; r++) c[i][j][r] = 0.f;

    int ia0 = tid * 2, ia1 = tid * 2 + 1;
    int am0 = ia0 >> 2, ak0 = (ia0 & 3) << 2;
    int am1 = ia1 >> 2, ak1 = (ia1 & 3) << 2;
    int br0 = ia0 >> 5, bc0 = (ia0 & 31) << 2;
    int br1 = ia1 >> 5, bc1 = (ia1 & 31) << 2;
    int nk = K / GBK;

    {
        int k0 = 0;
        cp_async16(smem_u32(rawA + am0 * GBK + ak0), A + (size_t)(m0 + am0) * K + k0 + ak0, (m0 + am0 < M) ? 16 : 0);
        cp_async16(smem_u32(rawA + am1 * GBK + ak1), A + (size_t)(m0 + am1) * K + k0 + ak1, (m0 + am1 < M) ? 16 : 0);
        cp_async16(smem_u32(rawB + br0 * GBN + bc0), B + (size_t)(k0 + br0) * Nc + n0 + bc0, 16);
        cp_async16(smem_u32(rawB + br1 * GBN + bc1), B + (size_t)(k0 + br1) * Nc + n0 + bc1, 16);
        asm volatile("cp.async.commit_group;");
    }

    for (int t = 0; t < nk; t++) {
        int buf = t & 1;
        bool more = (t + 1 < nk);
        if (more) {
            int k0 = (t + 1) * GBK;
            int nb = buf ^ 1;
            cp_async16(smem_u32(rawA + nb * RAW_A_F + am0 * GBK + ak0), A + (size_t)(m0 + am0) * K + k0 + ak0, (m0 + am0 < M) ? 16 : 0);
            cp_async16(smem_u32(rawA + nb * RAW_A_F + am1 * GBK + ak1), A + (size_t)(m0 + am1) * K + k0 + ak1, (m0 + am1 < M) ? 16 : 0);
            cp_async16(smem_u32(rawB + nb * RAW_B_F + br0 * GBN + bc0), B + (size_t)(k0 + br0) * Nc + n0 + bc0, 16);
            cp_async16(smem_u32(rawB + nb * RAW_B_F + br1 * GBN + bc1), B + (size_t)(k0 + br1) * Nc + n0 + bc1, 16);
            asm volatile("cp.async.commit_group;");
            asm volatile("cp.async.wait_group 1;");
        } else {
            asm volatile("cp.async.wait_group 0;");
        }
        __syncthreads();

        // split raw -> hi/lo (optional fused BN+ReLU on A)
        {
            const float* ra = rawA + buf * RAW_A_F;
            const float* rb2 = rawB + buf * RAW_B_F;
            float4 a0 = *(const float4*)(ra + am0 * GBK + ak0);
            float4 a1 = *(const float4*)(ra + am1 * GBK + ak1);
            if (Asc) {
                int cb0 = t * GBK + ak0;
                int cb1 = t * GBK + ak1;
                a0 = bnrelu4(a0, *(const float4*)(Asc + cb0), *(const float4*)(Ash + cb0));
                a1 = bnrelu4(a1, *(const float4*)(Asc + cb1), *(const float4*)(Ash + cb1));
            }
            uint32_t h, l;
            tf32split(a0.x, h, l); AHI(ak0 + 0, am0) = __uint_as_float(h); ALO(ak0 + 0, am0) = __uint_as_float(l);
            tf32split(a0.y, h, l); AHI(ak0 + 1, am0) = __uint_as_float(h); ALO(ak0 + 1, am0) = __uint_as_float(l);
            tf32split(a0.z, h, l); AHI(ak0 + 2, am0) = __uint_as_float(h); ALO(ak0 + 2, am0) = __uint_as_float(l);
            tf32split(a0.w, h, l); AHI(ak0 + 3, am0) = __uint_as_float(h); ALO(ak0 + 3, am0) = __uint_as_float(l);
            tf32split(a1.x, h, l); AHI(ak1 + 0, am1) = __uint_as_float(h); ALO(ak1 + 0, am1) = __uint_as_float(l);
            tf32split(a1.y, h, l); AHI(ak1 + 1, am1) = __uint_as_float(h); ALO(ak1 + 1, am1) = __uint_as_float(l);
            tf32split(a1.z, h, l); AHI(ak1 + 2, am1) = __uint_as_float(h); ALO(ak1 + 2, am1) = __uint_as_float(l);
            tf32split(a1.w, h, l); AHI(ak1 + 3, am1) = __uint_as_float(h); ALO(ak1 + 3, am1) = __uint_as_float(l);
            float4 b0 = *(const float4*)(rb2 + br0 * GBN + bc0);
            float4 b1 = *(const float4*)(rb2 + br1 * GBN + bc1);
            tf32split(b0.x, h, l); BHI(br0, bc0 + 0) = __uint_as_float(h); BLO(br0, bc0 + 0) = __uint_as_float(l);
            tf32split(b0.y, h, l); BHI(br0, bc0 + 1) = __uint_as_float(h); BLO(br0, bc0 + 1) = __uint_as_float(l);
            tf32split(b0.z, h, l); BHI(br0, bc0 + 2) = __uint_as_float(h); BLO(br0, bc0 + 2) = __uint_as_float(l);
            tf32split(b0.w, h, l); BHI(br0, bc0 + 3) = __uint_as_float(h); BLO(br0, bc0 + 3) = __uint_as_float(l);
            tf32split(b1.x, h, l); BHI(br1, bc1 + 0) = __uint_as_float(h); BLO(br1, bc1 + 0) = __uint_as_float(l);
            tf32split(b1.y, h, l); BHI(br1, bc1 + 1) = __uint_as_float(h); BLO(br1, bc1 + 1) = __uint_as_float(l);
            tf32split(b1.z, h, l); BHI(br1, bc1 + 2) = __uint_as_float(h); BLO(br1, bc1 + 2) = __uint_as_float(l);
            tf32split(b1.w, h, l); BHI(br1, bc1 + 3) = __uint_as_float(h); BLO(br1, bc1 + 3) = __uint_as_float(l);
        }
        __syncthreads();

        #pragma unroll
        for (int h8 = 0; h8 < 2; h8++) {
            int k8 = h8 * 8;
            uint32_t bh[4][2], bl[4][2];
            #pragma unroll
            for (int ni = 0; ni < 4; ni++) {
                int n = wn + 8 * ni + grp;
                bh[ni][0] = __float_as_uint(BHI(k8 + tig, n));
                bh[ni][1] = __float_as_uint(BHI(k8 + tig + 4, n));
                bl[ni][0] = __float_as_uint(BLO(k8 + tig, n));
                bl[ni][1] = __float_as_uint(BLO(k8 + tig + 4, n));
            }
            #pragma unroll
            for (int mi = 0; mi < 4; mi++) {
                int m = wm + 16 * mi + grp;
                uint32_t ah0 = __float_as_uint(AHI(k8 + tig, m));
                uint32_t ah1 = __float_as_uint(AHI(k8 + tig, m + 8));
                uint32_t ah2 = __float_as_uint(AHI(k8 + tig + 4, m));
                uint32_t ah3 = __float_as_uint(AHI(k8 + tig + 4, m + 8));
                uint32_t al0 = __float_as_uint(ALO(k8 + tig, m));
                uint32_t al1 = __float_as_uint(ALO(k8 + tig, m + 8));
                uint32_t al2 = __float_as_uint(ALO(k8 + tig + 4, m));
                uint32_t al3 = __float_as_uint(ALO(k8 + tig + 4, m + 8));
                #pragma unroll
                for (int ni = 0; ni < 4; ni++) {
                    mma_tf32(c[mi][ni], ah0, ah1, ah2, ah3, bh[ni][0], bh[ni][1]);
                    mma_tf32(c[mi][ni], ah0, ah1, ah2, ah3, bl[ni][0], bl[ni][1]);
                    mma_tf32(c[mi][ni], al0, al1, al2, al3, bh[ni][0], bh[ni][1]);
                }
            }
        }
    }

    #pragma unroll
    for (int mi = 0; mi < 4; mi++) {
        int r0 = m0 + wm + 16 * mi + grp;
        int r1 = r0 + 8;
        #pragma unroll
        for (int ni = 0; ni < 4; ni++) {
            int cc = n0 + wn + 8 * ni + 2 * tig;
            if (r0 < M) *(float2*)(C + (size_t)r0 * Nc + cc) = make_float2(c[mi][ni][0], c[mi][ni][1]);
            if (r1 < M) *(float2*)(C + (size_t)r1 * Nc + cc) = make_float2(c[mi][ni][2], c[mi][ni][3]);
        }
    }
#undef AHI
#undef ALO
#undef BHI
#undef BLO
}

// ---------------- small SGEMM for layer 3 (N=40), fused A = relu(bn2(A)) + relu(bn1(R)) ----------------
#define BM 64
#define BN 64
#define BKK 16
__global__ void __launch_bounds__(256) sgemm64(
    const float* __restrict__ A, const float* __restrict__ B, float* __restrict__ C,
    int M, int K, int Nc,
    const float* __restrict__ Asc, const float* __restrict__ Ash,
    const float* __restrict__ R, const float* __restrict__ Rsc, const float* __restrict__ Rsh)
{
    __shared__ float As[BKK][BM];
    __shared__ float Bs[BKK][BN];
    int tid = threadIdx.x;
    int tx = tid & 15, ty = tid >> 4;
    int m0 = blockIdx.y * BM;
    int n0 = blockIdx.x * BN;
    float acc[4][4] = {};

    int ar = tid >> 2;
    int ak = (tid & 3) * 4;
    int br = tid >> 4;
    int bc = (tid & 15) * 4;

    for (int k0 = 0; k0 < K; k0 += BKK) {
        float4 av = make_float4(0.f, 0.f, 0.f, 0.f);
        int am = m0 + ar;
        if (am < M) {
            av = *(const float4*)(A + (size_t)am * K + k0 + ak);
            int cb = k0 + ak;
            av = bnrelu4(av, *(const float4*)(Asc + cb), *(const float4*)(Ash + cb));
            float4 rv = *(const float4*)(R + (size_t)am * K + cb);
            float4 rr = bnrelu4(rv, *(const float4*)(Rsc + cb), *(const float4*)(Rsh + cb));
            av.x += rr.x; av.y += rr.y; av.z += rr.z; av.w += rr.w;
        }
        As[ak + 0][ar] = av.x; As[ak + 1][ar] = av.y;
        As[ak + 2][ar] = av.z; As[ak + 3][ar] = av.w;

        float4 bv = make_float4(0.f, 0.f, 0.f, 0.f);
        if (n0 + bc < Nc) bv = *(const float4*)(B + (size_t)(k0 + br) * Nc + n0 + bc);
        *(float4*)&Bs[br][bc] = bv;
        __syncthreads();

        #pragma unroll
        for (int kk = 0; kk < BKK; kk++) {
            float a[4], b[4];
            *(float4*)a = *(const float4*)&As[kk][ty * 4];
            *(float4*)b = *(const float4*)&Bs[kk][tx * 4];
            #pragma unroll
            for (int i = 0; i < 4; i++)
                #pragma unroll
                for (int j = 0; j < 4; j++)
                    acc[i][j] += a[i] * b[j];
        }
        __syncthreads();
    }
    #pragma unroll
    for (int i = 0; i < 4; i++) {
        int m = m0 + ty * 4 + i;
        if (m >= M) continue;
        #pragma unroll
        for (int j = 0; j < 4; j++) {
            int n = n0 + tx * 4 + j;
            if (n < Nc) C[(size_t)m * Nc + n] = acc[i][j];
        }
    }
}

// ---------------- CSR gather (broadcast loads, no smem, no barriers) + fused BN stats ----------------
__global__ void __launch_bounds__(64) gather256_bn(
    const float* __restrict__ h, const float* __restrict__ dinv,
    const float* __restrict__ bias, const int* __restrict__ rowoff,
    const int* __restrict__ csrc, const float* __restrict__ cw,
    float* __restrict__ out)
{
    int t = threadIdx.x;
    int c4 = t * 4;
    float4 bsc = *(const float4*)(bias + c4);
    float4 ssum = make_float4(0.f, 0.f, 0.f, 0.f);
    float4 ssq  = make_float4(0.f, 0.f, 0.f, 0.f);
    for (int i = blockIdx.x; i < NNODES; i += gridDim.x) {
        int beg = rowoff[i], end = rowoff[i + 1];
        float di = dinv[i];
        float w0 = di * di;
        float4 hv = *(const float4*)(h + (size_t)i * HDIM + c4);
        float4 acc;
        acc.x = fmaf(w0, hv.x, bsc.x);
        acc.y = fmaf(w0, hv.y, bsc.y);
        acc.z = fmaf(w0, hv.z, bsc.z);
        acc.w = fmaf(w0, hv.w, bsc.w);
        int j = beg;
        for (; j + 4 <= end; j += 4) {
            int s0 = csrc[j + 0], s1 = csrc[j + 1], s2 = csrc[j + 2], s3 = csrc[j + 3];
            float w1 = cw[j + 0], w2 = cw[j + 1], w3 = cw[j + 2], w4 = cw[j + 3];
            float4 a0 = *(const float4*)(h + (size_t)s0 * HDIM + c4);
            float4 a1 = *(const float4*)(h + (size_t)s1 * HDIM + c4);
            float4 a2 = *(const float4*)(h + (size_t)s2 * HDIM + c4);
            float4 a3 = *(const float4*)(h + (size_t)s3 * HDIM + c4);
            acc.x = fmaf(w1, a0.x, acc.x); acc.y = fmaf(w1, a0.y, acc.y);
            acc.z = fmaf(w1, a0.z, acc.z); acc.w = fmaf(w1, a0.w, acc.w);
            acc.x = fmaf(w2, a1.x, acc.x); acc.y = fmaf(w2, a1.y, acc.y);
            acc.z = fmaf(w2, a1.z, acc.z); acc.w = fmaf(w2, a1.w, acc.w);
            acc.x = fmaf(w3, a2.x, acc.x); acc.y = fmaf(w3, a2.y, acc.y);
            acc.z = fmaf(w3, a2.z, acc.z); acc.w = fmaf(w3, a2.w, acc.w);
            acc.x = fmaf(w4, a3.x, acc.x); acc.y = fmaf(w4, a3.y, acc.y);
            acc.z = fmaf(w4, a3.z, acc.z); acc.w = fmaf(w4, a3.w, acc.w);
        }
        for (; j < end; j++) {
            int s0 = csrc[j];
            float w1 = cw[j];
            float4 a0 = *(const float4*)(h + (size_t)s0 * HDIM + c4);
            acc.x = fmaf(w1, a0.x, acc.x); acc.y = fmaf(w1, a0.y, acc.y);
            acc.z = fmaf(w1, a0.z, acc.z); acc.w = fmaf(w1, a0.w, acc.w);
        }
        *(float4*)(out + (size_t)i * HDIM + c4) = acc;
        ssum.x += acc.x; ssum.y += acc.y; ssum.z += acc.z; ssum.w += acc.w;
        ssq.x = fmaf(acc.x, acc.x, ssq.x); ssq.y = fmaf(acc.y, acc.y, ssq.y);
        ssq.z = fmaf(acc.z, acc.z, ssq.z); ssq.w = fmaf(acc.w, acc.w, ssq.w);
    }
    atomicAdd(&g_bnsum[c4 + 0], ssum.x); atomicAdd(&g_bnsum[c4 + 1], ssum.y);
    atomicAdd(&g_bnsum[c4 + 2], ssum.z); atomicAdd(&g_bnsum[c4 + 3], ssum.w);
    atomicAdd(&g_bnsq[c4 + 0], ssq.x);  atomicAdd(&g_bnsq[c4 + 1], ssq.y);
    atomicAdd(&g_bnsq[c4 + 2], ssq.z);  atomicAdd(&g_bnsq[c4 + 3], ssq.w);
}

__global__ void __launch_bounds__(64) gather40(
    const float* __restrict__ h, const float* __restrict__ dinv,
    const float* __restrict__ bias, const int* __restrict__ rowoff,
    const int* __restrict__ csrc, const float* __restrict__ cw,
    float* __restrict__ out)
{
    int i = blockIdx.x;
    int c = threadIdx.x;
    if (c >= COUT) return;
    int beg = rowoff[i], end = rowoff[i + 1];
    float di = dinv[i];
    float acc = fmaf(di * di, h[(size_t)i * COUT + c], bias[c]);
    int j = beg;
    for (; j + 4 <= end; j += 4) {
        int s0 = csrc[j + 0], s1 = csrc[j + 1], s2 = csrc[j + 2], s3 = csrc[j + 3];
        float w1 = cw[j + 0], w2 = cw[j + 1], w3 = cw[j + 2], w4 = cw[j + 3];
        float a0 = h[(size_t)s0 * COUT + c];
        float a1 = h[(size_t)s1 * COUT + c];
        float a2 = h[(size_t)s2 * COUT + c];
        float a3 = h[(size_t)s3 * COUT + c];
        acc = fmaf(w1, a0, acc);
        acc = fmaf(w2, a1, acc);
        acc = fmaf(w3, a2, acc);
        acc = fmaf(w4, a3, acc);
    }
    for (; j < end; j++)
        acc = fmaf(cw[j], h[(size_t)csrc[j] * COUT + c], acc);
    out[(size_t)i * COUT + c] = acc;
}

// ---------------- batchnorm ----------------
__global__ void bn_zero() {
    int c = threadIdx.x;
    g_bnsum[c] = 0.f;
    g_bnsq[c]  = 0.f;
}
__global__ void bn_final(const float* __restrict__ gamma, const float* __restrict__ beta,
                         float* __restrict__ outScale, float* __restrict__ outShift) {
    int c = threadIdx.x;
    float invn = 1.f / (float)NNODES;
    float mean = g_bnsum[c] * invn;
    float var  = g_bnsq[c] * invn - mean * mean;
    float sc = gamma[c] * rsqrtf(var + EPS);
    outScale[c] = sc;
    outShift[c] = beta[c] - mean * sc;
}

// ---------------- log_softmax over 40 classes ----------------
__global__ void logsoftmax40(const float* __restrict__ x, float* __restrict__ out) {
    int g = blockIdx.x * blockDim.x + threadIdx.x;
    int row = g >> 5, lane = g & 31;
    if (row >= NNODES) return;
    const float* xr = x + (size_t)row * COUT;
    float v0 = xr[lane];
    float v1 = (lane + 32 < COUT) ? xr[lane + 32] : NEG_INF_F;
    float m = fmaxf(v0, v1);
    #pragma unroll
    for (int o = 16; o; o >>= 1) m = fmaxf(m, __shfl_xor_sync(0xffffffffu, m, o));
    float e0 = __expf(v0 - m);
    float e1 = (lane + 32 < COUT) ? __expf(v1 - m) : 0.f;
    float s = e0 + e1;
    #pragma unroll
    for (int o = 16; o; o >>= 1) s += __shfl_xor_sync(0xffffffffu, s, o);
    float ls = logf(s);
    out[(size_t)row * COUT + lane] = v0 - m - ls;
    if (lane + 32 < COUT) out[(size_t)row * COUT + lane + 32] = v1 - m - ls;
}

// ---------------- driver ----------------
extern "C" void kernel_launch(void* const* d_in, const int* in_sizes, int n_in,
                              void* d_out, int out_size)
{
    const float* x   = (const float*)d_in[0];
    const int*   ei  = (const int*)  d_in[1];
    const float* W1  = (const float*)d_in[2];
    const float* b1  = (const float*)d_in[3];
    const float* g1  = (const float*)d_in[4];
    const float* be1 = (const float*)d_in[5];
    const float* W2  = (const float*)d_in[6];
    const float* b2  = (const float*)d_in[7];
    const float* g2  = (const float*)d_in[8];
    const float* be2 = (const float*)d_in[9];
    const float* W3  = (const float*)d_in[10];
    const float* b3  = (const float*)d_in[11];
    float* out = (float*)d_out;

    int E = in_sizes[1] / 2;
    const int* src = ei;
    const int* dst = ei + E;

    float *h, *acc, *hin, *dinv, *cw, *sc1, *sh1, *sc2, *sh2;
    int *cnt, *rowoff, *cursor, *bsum, *csrc;
    cudaGetSymbolAddress((void**)&h,      g_h);
    cudaGetSymbolAddress((void**)&acc,    g_acc);
    cudaGetSymbolAddress((void**)&hin,    g_hin);
    cudaGetSymbolAddress((void**)&dinv,   g_dinv);
    cudaGetSymbolAddress((void**)&cnt,    g_cnt);
    cudaGetSymbolAddress((void**)&rowoff, g_rowoff);
    cudaGetSymbolAddress((void**)&cursor, g_cursor);
    cudaGetSymbolAddress((void**)&bsum,   g_blocksum);
    cudaGetSymbolAddress((void**)&csrc,   g_csr_src);
    cudaGetSymbolAddress((void**)&cw,     g_csr_w);
    cudaGetSymbolAddress((void**)&sc1,    g_scale1);
    cudaGetSymbolAddress((void**)&sh1,    g_shift1);
    cudaGetSymbolAddress((void**)&sc2,    g_scale2);
    cudaGetSymbolAddress((void**)&sh2,    g_shift2);

    cudaFuncSetAttribute(gemm_tf32, cudaFuncAttributeMaxDynamicSharedMemorySize, GEMM_SMEM_BYTES);

    const int T = 256;
    int nbN  = (NNODES + T - 1) / T;
    int nbE  = (E + T - 1) / T;
    int nbRow = (int)(((long long)NNODES * 32 + T - 1) / T);
    int nbScan = (NNODES + 1023) / 1024;
    dim3 gemmGrid(HDIM / GBN, (NNODES + GBM - 1) / GBM);
    dim3 gemmGrid40(1, (NNODES + 63) / 64);
    const int GB = 4096;

    // ---- degree/norm, then L1 GEMM early (profiled slot), then CSR ----
    cnt_zero<<<nbN, T>>>(cnt);
    deg_hist<<<nbE, T>>>(dst, cnt, E);
    dinv_k<<<nbN, T>>>(cnt, dinv);

    gemm_tf32<<<gemmGrid, T, GEMM_SMEM_BYTES>>>(x, W1, h, NNODES, FIN, HDIM, nullptr, nullptr);

    scan_block<<<nbScan, 256>>>(cnt, rowoff, bsum, NNODES);
    scan_sums<<<1, 256>>>(bsum, nbScan);
    scan_add<<<nbN, T>>>(rowoff, bsum, NNODES, E);
    cursor_copy<<<nbN, T>>>(rowoff, cursor);
    csr_place<<<nbE, T>>>(src, dst, dinv, cursor, csrc, cw, E);

    // ---- layer 1: gather -> acc (raw conv1 out, kept for residual) ----
    bn_zero<<<1, HDIM>>>();
    gather256_bn<<<GB, 64>>>(h, dinv, b1, rowoff, csrc, cw, acc);
    bn_final<<<1, HDIM>>>(g1, be1, sc1, sh1);

    // ---- layer 2: GEMM reads acc with fused bn1+relu; gather -> hin (raw conv2 out) ----
    gemm_tf32<<<gemmGrid, T, GEMM_SMEM_BYTES>>>(acc, W2, h, NNODES, HDIM, HDIM, sc1, sh1);
    bn_zero<<<1, HDIM>>>();
    gather256_bn<<<GB, 64>>>(h, dinv, b2, rowoff, csrc, cw, hin);
    bn_final<<<1, HDIM>>>(g2, be2, sc2, sh2);

    // ---- layer 3: A = relu(bn2(hin)) + relu(bn1(acc)) fused in sgemm64; C -> h (N x 40) ----
    sgemm64<<<gemmGrid40, T>>>(hin, W3, h, NNODES, HDIM, COUT, sc2, sh2, acc, sc1, sh1);
    gather40<<<NNODES, 64>>>(h, dinv, b3, rowoff, csrc, cw, hin);   // hin reused as N x 40
    logsoftmax40<<<nbRow, T>>>(hin, out);
}

// round 16
// speedup vs baseline: 1.0363x; 1.0262x over previous
#include <cuda_runtime.h>
#include <cstdint>
#include <math.h>

#define NEG_INF_F __int_as_float(0xff800000)

#define NNODES 169343
#define HDIM   256
#define FIN    128
#define COUT   40
#define EPS    1e-5f
#define EMAX   2500000

// ---------------- scratch (no allocations allowed) ----------------
__device__ float g_h  [(size_t)NNODES * HDIM];
__device__ float g_acc[(size_t)NNODES * HDIM];
__device__ float g_hin[(size_t)NNODES * HDIM];
__device__ float g_dinv[NNODES];
__device__ int   g_cnt [NNODES];
__device__ int   g_rowoff[NNODES + 1];
__device__ int   g_cursor[NNODES];
__device__ int   g_blocksum[512];
__device__ int   g_csr_src[EMAX];
__device__ float g_csr_w [EMAX];
__device__ float g_bnsum[HDIM];
__device__ float g_bnsq [HDIM];
__device__ float g_scale1[HDIM];
__device__ float g_shift1[HDIM];
__device__ float g_scale2[HDIM];
__device__ float g_shift2[HDIM];
__device__ float g_whi[HDIM * HDIM];
__device__ float g_wlo[HDIM * HDIM];

// ---------------- degree / norm ----------------
__global__ void cnt_zero(int* cnt) {
    int i = blockIdx.x * blockDim.x + threadIdx.x;
    if (i < NNODES) cnt[i] = 0;
}
__global__ void deg_hist(const int* __restrict__ dst, int* __restrict__ cnt, int E) {
    int e = blockIdx.x * blockDim.x + threadIdx.x;
    if (e < E) atomicAdd(&cnt[dst[e]], 1);
}
__global__ void dinv_k(const int* __restrict__ cnt, float* __restrict__ dinv) {
    int i = blockIdx.x * blockDim.x + threadIdx.x;
    if (i < NNODES) dinv[i] = rsqrtf((float)(cnt[i] + 1));
}

// ---------------- exclusive scan ----------------
__global__ void scan_block(const int* __restrict__ in, int* __restrict__ out,
                           int* __restrict__ bsum, int n)
{
    __shared__ int wsum[8];
    __shared__ int woff[8];
    int t = threadIdx.x;
    int base = blockIdx.x * 1024 + t * 4;
    int val[4], inc[4];
    int s = 0;
    #pragma unroll
    for (int k = 0; k < 4; k++) {
        val[k] = (base + k < n) ? in[base + k] : 0;
        s += val[k];
        inc[k] = s;
    }
    int lane = t & 31, wid = t >> 5;
    int x = s;
    #pragma unroll
    for (int o = 1; o < 32; o <<= 1) {
        int y = __shfl_up_sync(0xffffffffu, x, o);
        if (lane >= o) x += y;
    }
    if (lane == 31) wsum[wid] = x;
    __syncthreads();
    if (t == 0) {
        int a = 0;
        #pragma unroll
        for (int w = 0; w < 8; w++) { woff[w] = a; a += wsum[w]; }
        bsum[blockIdx.x] = a;
    }
    __syncthreads();
    int tb = woff[wid] + x - s;
    #pragma unroll
    for (int k = 0; k < 4; k++)
        if (base + k < n) out[base + k] = tb + inc[k] - val[k];
}
__global__ void scan_sums(int* __restrict__ bsum, int nb) {
    __shared__ int wsum[8];
    __shared__ int woff[8];
    int t = threadIdx.x;
    int v = (t < nb) ? bsum[t] : 0;
    int lane = t & 31, wid = t >> 5;
    int x = v;
    #pragma unroll
    for (int o = 1; o < 32; o <<= 1) {
        int y = __shfl_up_sync(0xffffffffu, x, o);
        if (lane >= o) x += y;
    }
    if (lane == 31) wsum[wid] = x;
    __syncthreads();
    if (t == 0) {
        int a = 0;
        #pragma unroll
        for (int w = 0; w < 8; w++) { woff[w] = a; a += wsum[w]; }
    }
    __syncthreads();
    if (t < nb) bsum[t] = woff[wid] + x - v;
}
__global__ void scan_add(int* __restrict__ out, const int* __restrict__ bsum, int n, int E) {
    int i = blockIdx.x * blockDim.x + threadIdx.x;
    if (i < n) out[i] += bsum[i >> 10];
    if (i == 0) out[n] = E;
}
__global__ void cursor_copy(const int* __restrict__ rowoff, int* __restrict__ cur) {
    int i = blockIdx.x * blockDim.x + threadIdx.x;
    if (i < NNODES) cur[i] = rowoff[i];
}
__global__ void csr_place(const int* __restrict__ src, const int* __restrict__ dst,
                          const float* __restrict__ dinv, int* __restrict__ cur,
                          int* __restrict__ csrc, float* __restrict__ cw, int E)
{
    int e = blockIdx.x * blockDim.x + threadIdx.x;
    if (e >= E) return;
    int s = src[e], d = dst[e];
    int pos = atomicAdd(&cur[d], 1);
    csrc[pos] = s;
    cw[pos] = dinv[s] * dinv[d];
}

// ---------------- tf32 split helpers ----------------
__device__ __forceinline__ void tf32split(float x, uint32_t& hi, uint32_t& lo) {
    uint32_t xb = __float_as_uint(x);
    uint32_t h = xb & 0xFFFFE000u;
    float l = x - __uint_as_float(h);
    uint32_t lb;
    asm("cvt.rna.tf32.f32 %0, %1;" : "=r"(lb) : "f"(l));
    hi = h; lo = lb;
}
__device__ __forceinline__ void mma_tf32(float* c, uint32_t a0, uint32_t a1,
                                         uint32_t a2, uint32_t a3,
                                         uint32_t b0, uint32_t b1) {
    asm volatile(
        "mma.sync.aligned.m16n8k8.row.col.f32.tf32.tf32.f32 "
        "{%0,%1,%2,%3}, {%4,%5,%6,%7}, {%8,%9}, {%0,%1,%2,%3};"
        : "+f"(c[0]), "+f"(c[1]), "+f"(c[2]), "+f"(c[3])
        : "r"(a0), "r"(a1), "r"(a2), "r"(a3), "r"(b0), "r"(b1));
}
__device__ __forceinline__ uint32_t smem_u32(const void* p) {
    return (uint32_t)__cvta_generic_to_shared(p);
}
__device__ __forceinline__ void cp_async16(uint32_t dst, const void* src, int sz) {
    asm volatile("cp.async.cg.shared.global [%0], [%1], 16, %2;"
                 :: "r"(dst), "l"(src), "r"(sz));
}
__device__ __forceinline__ float4 bnrelu4(float4 v, float4 s, float4 sh) {
    float4 r;
    r.x = fmaxf(fmaf(v.x, s.x, sh.x), 0.f);
    r.y = fmaxf(fmaf(v.y, s.y, sh.y), 0.f);
    r.z = fmaxf(fmaf(v.z, s.z, sh.z), 0.f);
    r.w = fmaxf(fmaf(v.w, s.w, sh.w), 0.f);
    return r;
}

// ---------------- weight pre-split ----------------
__global__ void wsplit(const float* __restrict__ W, float* __restrict__ whi,
                       float* __restrict__ wlo, int n) {
    int i = blockIdx.x * blockDim.x + threadIdx.x;
    if (i < n) {
        uint32_t h, l;
        tf32split(W[i], h, l);
        whi[i] = __uint_as_float(h);
        wlo[i] = __uint_as_float(l);
    }
}

// ---------------- tensor-core GEMM: 128x128x16, 3xTF32, pre-split B, 2 CTA/SM ----------------
#define GBM 128
#define GBN 128
#define GBK 16
#define SST 136
#define RAW_A_F (GBM * GBK)        // 2048
#define BT_F (GBK * SST)           // 2176
#define GEMM_SMEM_BYTES ((2 * RAW_A_F + 2 * BT_F + 4 * BT_F) * 4)

__global__ void __launch_bounds__(256, 2) gemm_tf32(
    const float* __restrict__ A,
    const float* __restrict__ Bhi, const float* __restrict__ Blo,
    float* __restrict__ C,
    int M, int K, int Nc,
    const float* __restrict__ Asc, const float* __restrict__ Ash)
{
    extern __shared__ float smem[];
    float* rawA = smem;                        // [2][GBM][GBK]
    float* Ahi  = rawA + 2 * RAW_A_F;          // [GBK][SST]
    float* Alo  = Ahi + BT_F;
    float* Bh2  = Alo + BT_F;                  // [2][GBK][SST]
    float* Bl2  = Bh2 + 2 * BT_F;              // [2][GBK][SST]
#define AHI(k, m) Ahi[(k) * SST + (m)]
#define ALO(k, m) Alo[(k) * SST + (m)]

    int tid = threadIdx.x;
    int warp = tid >> 5, lane = tid & 31;
    int m0 = blockIdx.y * GBM, n0 = blockIdx.x * GBN;
    int wm = (warp >> 2) * 64;
    int wn = (warp & 3) * 32;
    int grp = lane >> 2, tig = lane & 3;

    float c[4][4][4];
    #pragma unroll
    for (int i = 0; i < 4; i++)
        #pragma unroll
        for (int j = 0; j < 4; j++)
            #pragma unroll
            for (int r = 0; r < 4; r++) c[i][j][r] = 0.f;

    // per-thread copy slots: 2 float4 of A + 2 float4 each of Bhi/Blo per tile
    int ia0 = tid * 2, ia1 = tid * 2 + 1;
    int am0 = ia0 >> 2, ak0 = (ia0 & 3) << 2;
    int am1 = ia1 >> 2, ak1 = (ia1 & 3) << 2;
    int br0 = ia0 >> 5, bc0 = (ia0 & 31) << 2;
    int br1 = ia1 >> 5, bc1 = (ia1 & 31) << 2;
    int nk = K / GBK;

    // prologue: tile 0 -> buffer 0
    {
        cp_async16(smem_u32(rawA + am0 * GBK + ak0), A + (size_t)(m0 + am0) * K + ak0, (m0 + am0 < M) ? 16 : 0);
        cp_async16(smem_u32(rawA + am1 * GBK + ak1), A + (size_t)(m0 + am1) * K + ak1, (m0 + am1 < M) ? 16 : 0);
        cp_async16(smem_u32(Bh2 + br0 * SST + bc0), Bhi + (size_t)br0 * Nc + n0 + bc0, 16);
        cp_async16(smem_u32(Bh2 + br1 * SST + bc1), Bhi + (size_t)br1 * Nc + n0 + bc1, 16);
        cp_async16(smem_u32(Bl2 + br0 * SST + bc0), Blo + (size_t)br0 * Nc + n0 + bc0, 16);
        cp_async16(smem_u32(Bl2 + br1 * SST + bc1), Blo + (size_t)br1 * Nc + n0 + bc1, 16);
        asm volatile("cp.async.commit_group;");
    }

    for (int t = 0; t < nk; t++) {
        int buf = t & 1;
        asm volatile("cp.async.wait_group 0;");
        __syncthreads();   // sync1: tile t complete + all threads past compute t-1

        // split A raw[buf] -> Ahi/Alo (optional fused BN+ReLU)
        {
            const float* ra = rawA + buf * RAW_A_F;
            float4 a0 = *(const float4*)(ra + am0 * GBK + ak0);
            float4 a1 = *(const float4*)(ra + am1 * GBK + ak1);
            if (Asc) {
                int cb0 = t * GBK + ak0;
                int cb1 = t * GBK + ak1;
                a0 = bnrelu4(a0, *(const float4*)(Asc + cb0), *(const float4*)(Ash + cb0));
                a1 = bnrelu4(a1, *(const float4*)(Asc + cb1), *(const float4*)(Ash + cb1));
            }
            uint32_t h, l;
            tf32split(a0.x, h, l); AHI(ak0 + 0, am0) = __uint_as_float(h); ALO(ak0 + 0, am0) = __uint_as_float(l);
            tf32split(a0.y, h, l); AHI(ak0 + 1, am0) = __uint_as_float(h); ALO(ak0 + 1, am0) = __uint_as_float(l);
            tf32split(a0.z, h, l); AHI(ak0 + 2, am0) = __uint_as_float(h); ALO(ak0 + 2, am0) = __uint_as_float(l);
            tf32split(a0.w, h, l); AHI(ak0 + 3, am0) = __uint_as_float(h); ALO(ak0 + 3, am0) = __uint_as_float(l);
            tf32split(a1.x, h, l); AHI(ak1 + 0, am1) = __uint_as_float(h); ALO(ak1 + 0, am1) = __uint_as_float(l);
            tf32split(a1.y, h, l); AHI(ak1 + 1, am1) = __uint_as_float(h); ALO(ak1 + 1, am1) = __uint_as_float(l);
            tf32split(a1.z, h, l); AHI(ak1 + 2, am1) = __uint_as_float(h); ALO(ak1 + 2, am1) = __uint_as_float(l);
            tf32split(a1.w, h, l); AHI(ak1 + 3, am1) = __uint_as_float(h); ALO(ak1 + 3, am1) = __uint_as_float(l);
        }
        __syncthreads();   // sync2: Ahi/Alo ready; safe to prefetch into buf^1

        // prefetch tile t+1 (overlaps with compute below)
        if (t + 1 < nk) {
            int k0 = (t + 1) * GBK;
            int nb = buf ^ 1;
            cp_async16(smem_u32(rawA + nb * RAW_A_F + am0 * GBK + ak0), A + (size_t)(m0 + am0) * K + k0 + ak0, (m0 + am0 < M) ? 16 : 0);
            cp_async16(smem_u32(rawA + nb * RAW_A_F + am1 * GBK + ak1), A + (size_t)(m0 + am1) * K + k0 + ak1, (m0 + am1 < M) ? 16 : 0);
            cp_async16(smem_u32(Bh2 + nb * BT_F + br0 * SST + bc0), Bhi + (size_t)(k0 + br0) * Nc + n0 + bc0, 16);
            cp_async16(smem_u32(Bh2 + nb * BT_F + br1 * SST + bc1), Bhi + (size_t)(k0 + br1) * Nc + n0 + bc1, 16);
            cp_async16(smem_u32(Bl2 + nb * BT_F + br0 * SST + bc0), Blo + (size_t)(k0 + br0) * Nc + n0 + bc0, 16);
            cp_async16(smem_u32(Bl2 + nb * BT_F + br1 * SST + bc1), Blo + (size_t)(k0 + br1) * Nc + n0 + bc1, 16);
            asm volatile("cp.async.commit_group;");
        }

        // compute 2 x k8
        const float* bh = Bh2 + buf * BT_F;
        const float* bl = Bl2 + buf * BT_F;
        #pragma unroll
        for (int h8 = 0; h8 < 2; h8++) {
            int k8 = h8 * 8;
            uint32_t bhf[4][2], blf[4][2];
            #pragma unroll
            for (int ni = 0; ni < 4; ni++) {
                int n = wn + 8 * ni + grp;
                bhf[ni][0] = __float_as_uint(bh[(k8 + tig) * SST + n]);
                bhf[ni][1] = __float_as_uint(bh[(k8 + tig + 4) * SST + n]);
                blf[ni][0] = __float_as_uint(bl[(k8 + tig) * SST + n]);
                blf[ni][1] = __float_as_uint(bl[(k8 + tig + 4) * SST + n]);
            }
            #pragma unroll
            for (int mi = 0; mi < 4; mi++) {
                int m = wm + 16 * mi + grp;
                uint32_t ah0 = __float_as_uint(AHI(k8 + tig, m));
                uint32_t ah1 = __float_as_uint(AHI(k8 + tig, m + 8));
                uint32_t ah2 = __float_as_uint(AHI(k8 + tig + 4, m));
                uint32_t ah3 = __float_as_uint(AHI(k8 + tig + 4, m + 8));
                uint32_t al0 = __float_as_uint(ALO(k8 + tig, m));
                uint32_t al1 = __float_as_uint(ALO(k8 + tig, m + 8));
                uint32_t al2 = __float_as_uint(ALO(k8 + tig + 4, m));
                uint32_t al3 = __float_as_uint(ALO(k8 + tig + 4, m + 8));
                #pragma unroll
                for (int ni = 0; ni < 4; ni++) {
                    mma_tf32(c[mi][ni], ah0, ah1, ah2, ah3, bhf[ni][0], bhf[ni][1]);
                    mma_tf32(c[mi][ni], ah0, ah1, ah2, ah3, blf[ni][0], blf[ni][1]);
                    mma_tf32(c[mi][ni], al0, al1, al2, al3, bhf[ni][0], bhf[ni][1]);
                }
            }
        }
    }

    #pragma unroll
    for (int mi = 0; mi < 4; mi++) {
        int r0 = m0 + wm + 16 * mi + grp;
        int r1 = r0 + 8;
        #pragma unroll
        for (int ni = 0; ni < 4; ni++) {
            int cc = n0 + wn + 8 * ni + 2 * tig;
            if (r0 < M) *(float2*)(C + (size_t)r0 * Nc + cc) = make_float2(c[mi][ni][0], c[mi][ni][1]);
            if (r1 < M) *(float2*)(C + (size_t)r1 * Nc + cc) = make_float2(c[mi][ni][2], c[mi][ni][3]);
        }
    }
#undef AHI
#undef ALO
}

// ---------------- small SGEMM for layer 3 (N=40), fused A = relu(bn2(A)) + relu(bn1(R)) ----------------
#define BM 64
#define BN 64
#define BKK 16
__global__ void __launch_bounds__(256) sgemm64(
    const float* __restrict__ A, const float* __restrict__ B, float* __restrict__ C,
    int M, int K, int Nc,
    const float* __restrict__ Asc, const float* __restrict__ Ash,
    const float* __restrict__ R, const float* __restrict__ Rsc, const float* __restrict__ Rsh)
{
    __shared__ float As[BKK][BM];
    __shared__ float Bs[BKK][BN];
    int tid = threadIdx.x;
    int tx = tid & 15, ty = tid >> 4;
    int m0 = blockIdx.y * BM;
    int n0 = blockIdx.x * BN;
    float acc[4][4] = {};

    int ar = tid >> 2;
    int ak = (tid & 3) * 4;
    int br = tid >> 4;
    int bc = (tid & 15) * 4;

    for (int k0 = 0; k0 < K; k0 += BKK) {
        float4 av = make_float4(0.f, 0.f, 0.f, 0.f);
        int am = m0 + ar;
        if (am < M) {
            av = *(const float4*)(A + (size_t)am * K + k0 + ak);
            int cb = k0 + ak;
            av = bnrelu4(av, *(const float4*)(Asc + cb), *(const float4*)(Ash + cb));
            float4 rv = *(const float4*)(R + (size_t)am * K + cb);
            float4 rr = bnrelu4(rv, *(const float4*)(Rsc + cb), *(const float4*)(Rsh + cb));
            av.x += rr.x; av.y += rr.y; av.z += rr.z; av.w += rr.w;
        }
        As[ak + 0][ar] = av.x; As[ak + 1][ar] = av.y;
        As[ak + 2][ar] = av.z; As[ak + 3][ar] = av.w;

        float4 bv = make_float4(0.f, 0.f, 0.f, 0.f);
        if (n0 + bc < Nc) bv = *(const float4*)(B + (size_t)(k0 + br) * Nc + n0 + bc);
        *(float4*)&Bs[br][bc] = bv;
        __syncthreads();

        #pragma unroll
        for (int kk = 0; kk < BKK; kk++) {
            float a[4], b[4];
            *(float4*)a = *(const float4*)&As[kk][ty * 4];
            *(float4*)b = *(const float4*)&Bs[kk][tx * 4];
            #pragma unroll
            for (int i = 0; i < 4; i++)
                #pragma unroll
                for (int j = 0; j < 4; j++)
                    acc[i][j] += a[i] * b[j];
        }
        __syncthreads();
    }
    #pragma unroll
    for (int i = 0; i < 4; i++) {
        int m = m0 + ty * 4 + i;
        if (m >= M) continue;
        #pragma unroll
        for (int j = 0; j < 4; j++) {
            int n = n0 + tx * 4 + j;
            if (n < Nc) C[(size_t)m * Nc + n] = acc[i][j];
        }
    }
}

// ---------------- CSR gather (R13 staged form) + fused BN stats ----------------
__global__ void __launch_bounds__(64) gather256_bn(
    const float* __restrict__ h, const float* __restrict__ dinv,
    const float* __restrict__ bias, const int* __restrict__ rowoff,
    const int* __restrict__ csrc, const float* __restrict__ cw,
    float* __restrict__ out)
{
    __shared__ int   ss[64];
    __shared__ float sw[64];
    int t = threadIdx.x;
    int c4 = t * 4;
    float4 bsc = *(const float4*)(bias + c4);
    float4 ssum = make_float4(0.f, 0.f, 0.f, 0.f);
    float4 ssq  = make_float4(0.f, 0.f, 0.f, 0.f);
    for (int i = blockIdx.x; i < NNODES; i += gridDim.x) {
        int beg = rowoff[i], end = rowoff[i + 1];
        float di = dinv[i];
        float w0 = di * di;
        float4 hv = *(const float4*)(h + (size_t)i * HDIM + c4);
        float4 acc;
        acc.x = fmaf(w0, hv.x, bsc.x);
        acc.y = fmaf(w0, hv.y, bsc.y);
        acc.z = fmaf(w0, hv.z, bsc.z);
        acc.w = fmaf(w0, hv.w, bsc.w);
        for (int off = beg; off < end; off += 64) {
            int m = min(64, end - off);
            if (t < m) { ss[t] = csrc[off + t]; sw[t] = cw[off + t]; }
            __syncthreads();
            int j = 0;
            for (; j + 4 <= m; j += 4) {
                float4 a0 = *(const float4*)(h + (size_t)ss[j + 0] * HDIM + c4);
                float4 a1 = *(const float4*)(h + (size_t)ss[j + 1] * HDIM + c4);
                float4 a2 = *(const float4*)(h + (size_t)ss[j + 2] * HDIM + c4);
                float4 a3 = *(const float4*)(h + (size_t)ss[j + 3] * HDIM + c4);
                float w1 = sw[j + 0], w2 = sw[j + 1], w3 = sw[j + 2], w4 = sw[j + 3];
                acc.x = fmaf(w1, a0.x, acc.x); acc.y = fmaf(w1, a0.y, acc.y);
                acc.z = fmaf(w1, a0.z, acc.z); acc.w = fmaf(w1, a0.w, acc.w);
                acc.x = fmaf(w2, a1.x, acc.x); acc.y = fmaf(w2, a1.y, acc.y);
                acc.z = fmaf(w2, a1.z, acc.z); acc.w = fmaf(w2, a1.w, acc.w);
                acc.x = fmaf(w3, a2.x, acc.x); acc.y = fmaf(w3, a2.y, acc.y);
                acc.z = fmaf(w3, a2.z, acc.z); acc.w = fmaf(w3, a2.w, acc.w);
                acc.x = fmaf(w4, a3.x, acc.x); acc.y = fmaf(w4, a3.y, acc.y);
                acc.z = fmaf(w4, a3.z, acc.z); acc.w = fmaf(w4, a3.w, acc.w);
            }
            for (; j < m; j++) {
                float4 a0 = *(const float4*)(h + (size_t)ss[j] * HDIM + c4);
                float w1 = sw[j];
                acc.x = fmaf(w1, a0.x, acc.x); acc.y = fmaf(w1, a0.y, acc.y);
                acc.z = fmaf(w1, a0.z, acc.z); acc.w = fmaf(w1, a0.w, acc.w);
            }
            __syncthreads();
        }
        *(float4*)(out + (size_t)i * HDIM + c4) = acc;
        ssum.x += acc.x; ssum.y += acc.y; ssum.z += acc.z; ssum.w += acc.w;
        ssq.x = fmaf(acc.x, acc.x, ssq.x); ssq.y = fmaf(acc.y, acc.y, ssq.y);
        ssq.z = fmaf(acc.z, acc.z, ssq.z); ssq.w = fmaf(acc.w, acc.w, ssq.w);
    }
    atomicAdd(&g_bnsum[c4 + 0], ssum.x); atomicAdd(&g_bnsum[c4 + 1], ssum.y);
    atomicAdd(&g_bnsum[c4 + 2], ssum.z); atomicAdd(&g_bnsum[c4 + 3], ssum.w);
    atomicAdd(&g_bnsq[c4 + 0], ssq.x);  atomicAdd(&g_bnsq[c4 + 1], ssq.y);
    atomicAdd(&g_bnsq[c4 + 2], ssq.z);  atomicAdd(&g_bnsq[c4 + 3], ssq.w);
}

__global__ void __launch_bounds__(64) gather40(
    const float* __restrict__ h, const float* __restrict__ dinv,
    const float* __restrict__ bias, const int* __restrict__ rowoff,
    const int* __restrict__ csrc, const float* __restrict__ cw,
    float* __restrict__ out)
{
    __shared__ int   ss[64];
    __shared__ float sw[64];
    int i = blockIdx.x;
    int c = threadIdx.x;
    int beg = rowoff[i], end = rowoff[i + 1];
    float di = dinv[i];
    float acc = 0.f;
    if (c < COUT) acc = fmaf(di * di, h[(size_t)i * COUT + c], bias[c]);
    for (int off = beg; off < end; off += 64) {
        int m = min(64, end - off);
        if (c < m) { ss[c] = csrc[off + c]; sw[c] = cw[off + c]; }
        __syncthreads();
        if (c < COUT) {
            int j = 0;
            for (; j + 4 <= m; j += 4) {
                float a0 = h[(size_t)ss[j + 0] * COUT + c];
                float a1 = h[(size_t)ss[j + 1] * COUT + c];
                float a2 = h[(size_t)ss[j + 2] * COUT + c];
                float a3 = h[(size_t)ss[j + 3] * COUT + c];
                acc = fmaf(sw[j + 0], a0, acc);
                acc = fmaf(sw[j + 1], a1, acc);
                acc = fmaf(sw[j + 2], a2, acc);
                acc = fmaf(sw[j + 3], a3, acc);
            }
            for (; j < m; j++)
                acc = fmaf(sw[j], h[(size_t)ss[j] * COUT + c], acc);
        }
        __syncthreads();
    }
    if (c < COUT) out[(size_t)i * COUT + c] = acc;
}

// ---------------- batchnorm ----------------
__global__ void bn_zero() {
    int c = threadIdx.x;
    g_bnsum[c] = 0.f;
    g_bnsq[c]  = 0.f;
}
__global__ void bn_final(const float* __restrict__ gamma, const float* __restrict__ beta,
                         float* __restrict__ outScale, float* __restrict__ outShift) {
    int c = threadIdx.x;
    float invn = 1.f / (float)NNODES;
    float mean = g_bnsum[c] * invn;
    float var  = g_bnsq[c] * invn - mean * mean;
    float sc = gamma[c] * rsqrtf(var + EPS);
    outScale[c] = sc;
    outShift[c] = beta[c] - mean * sc;
}

// ---------------- log_softmax over 40 classes ----------------
__global__ void logsoftmax40(const float* __restrict__ x, float* __restrict__ out) {
    int g = blockIdx.x * blockDim.x + threadIdx.x;
    int row = g >> 5, lane = g & 31;
    if (row >= NNODES) return;
    const float* xr = x + (size_t)row * COUT;
    float v0 = xr[lane];
    float v1 = (lane + 32 < COUT) ? xr[lane + 32] : NEG_INF_F;
    float m = fmaxf(v0, v1);
    #pragma unroll
    for (int o = 16; o; o >>= 1) m = fmaxf(m, __shfl_xor_sync(0xffffffffu, m, o));
    float e0 = __expf(v0 - m);
    float e1 = (lane + 32 < COUT) ? __expf(v1 - m) : 0.f;
    float s = e0 + e1;
    #pragma unroll
    for (int o = 16; o; o >>= 1) s += __shfl_xor_sync(0xffffffffu, s, o);
    float ls = logf(s);
    out[(size_t)row * COUT + lane] = v0 - m - ls;
    if (lane + 32 < COUT) out[(size_t)row * COUT + lane + 32] = v1 - m - ls;
}

// ---------------- driver ----------------
extern "C" void kernel_launch(void* const* d_in, const int* in_sizes, int n_in,
                              void* d_out, int out_size)
{
    const float* x   = (const float*)d_in[0];
    const int*   ei  = (const int*)  d_in[1];
    const float* W1  = (const float*)d_in[2];
    const float* b1  = (const float*)d_in[3];
    const float* g1  = (const float*)d_in[4];
    const float* be1 = (const float*)d_in[5];
    const float* W2  = (const float*)d_in[6];
    const float* b2  = (const float*)d_in[7];
    const float* g2  = (const float*)d_in[8];
    const float* be2 = (const float*)d_in[9];
    const float* W3  = (const float*)d_in[10];
    const float* b3  = (const float*)d_in[11];
    float* out = (float*)d_out;

    int E = in_sizes[1] / 2;
    const int* src = ei;
    const int* dst = ei + E;

    float *h, *acc, *hin, *dinv, *cw, *sc1, *sh1, *sc2, *sh2, *whi, *wlo;
    int *cnt, *rowoff, *cursor, *bsum, *csrc;
    cudaGetSymbolAddress((void**)&h,      g_h);
    cudaGetSymbolAddress((void**)&acc,    g_acc);
    cudaGetSymbolAddress((void**)&hin,    g_hin);
    cudaGetSymbolAddress((void**)&dinv,   g_dinv);
    cudaGetSymbolAddress((void**)&cnt,    g_cnt);
    cudaGetSymbolAddress((void**)&rowoff, g_rowoff);
    cudaGetSymbolAddress((void**)&cursor, g_cursor);
    cudaGetSymbolAddress((void**)&bsum,   g_blocksum);
    cudaGetSymbolAddress((void**)&csrc,   g_csr_src);
    cudaGetSymbolAddress((void**)&cw,     g_csr_w);
    cudaGetSymbolAddress((void**)&sc1,    g_scale1);
    cudaGetSymbolAddress((void**)&sh1,    g_shift1);
    cudaGetSymbolAddress((void**)&sc2,    g_scale2);
    cudaGetSymbolAddress((void**)&sh2,    g_shift2);
    cudaGetSymbolAddress((void**)&whi,    g_whi);
    cudaGetSymbolAddress((void**)&wlo,    g_wlo);

    cudaFuncSetAttribute(gemm_tf32, cudaFuncAttributeMaxDynamicSharedMemorySize, GEMM_SMEM_BYTES);

    const int T = 256;
    int nbN  = (NNODES + T - 1) / T;
    int nbE  = (E + T - 1) / T;
    int nbRow = (int)(((long long)NNODES * 32 + T - 1) / T);
    int nbScan = (NNODES + 1023) / 1024;
    dim3 gemmGrid(HDIM / GBN, (NNODES + GBM - 1) / GBM);
    dim3 gemmGrid40(1, (NNODES + 63) / 64);
    const int GB = 4096;

    // ---- degree/norm, W1 split, L1 GEMM (profiled slot), then CSR ----
    cnt_zero<<<nbN, T>>>(cnt);
    deg_hist<<<nbE, T>>>(dst, cnt, E);
    dinv_k<<<nbN, T>>>(cnt, dinv);
    wsplit<<<(FIN * HDIM + T - 1) / T, T>>>(W1, whi, wlo, FIN * HDIM);

    gemm_tf32<<<gemmGrid, T, GEMM_SMEM_BYTES>>>(x, whi, wlo, h, NNODES, FIN, HDIM, nullptr, nullptr);

    scan_block<<<nbScan, 256>>>(cnt, rowoff, bsum, NNODES);
    scan_sums<<<1, 256>>>(bsum, nbScan);
    scan_add<<<nbN, T>>>(rowoff, bsum, NNODES, E);
    cursor_copy<<<nbN, T>>>(rowoff, cursor);
    csr_place<<<nbE, T>>>(src, dst, dinv, cursor, csrc, cw, E);

    // ---- layer 1: gather -> acc (raw conv1 out, kept for residual) ----
    bn_zero<<<1, HDIM>>>();
    gather256_bn<<<GB, 64>>>(h, dinv, b1, rowoff, csrc, cw, acc);
    bn_final<<<1, HDIM>>>(g1, be1, sc1, sh1);

    // ---- layer 2: split W2; GEMM reads acc with fused bn1+relu; gather -> hin ----
    wsplit<<<(HDIM * HDIM + T - 1) / T, T>>>(W2, whi, wlo, HDIM * HDIM);
    gemm_tf32<<<gemmGrid, T, GEMM_SMEM_BYTES>>>(acc, whi, wlo, h, NNODES, HDIM, HDIM, sc1, sh1);
    bn_zero<<<1, HDIM>>>();
    gather256_bn<<<GB, 64>>>(h, dinv, b2, rowoff, csrc, cw, hin);
    bn_final<<<1, HDIM>>>(g2, be2, sc2, sh2);

    // ---- layer 3: A = relu(bn2(hin)) + relu(bn1(acc)) fused in sgemm64; C -> h (N x 40) ----
    sgemm64<<<gemmGrid40, T>>>(hin, W3, h, NNODES, HDIM, COUT, sc2, sh2, acc, sc1, sh1);
    gather40<<<NNODES, 64>>>(h, dinv, b3, rowoff, csrc, cw, hin);
    logsoftmax40<<<nbRow, T>>>(hin, out);
}